// round 15
// baseline (speedup 1.0000x reference)
#include <cuda_runtime.h>
#include <cuda_fp16.h>
#include <cstdint>

#define D 128
#define N_MAX 50064
#define E_MAX 500000
#define FB 160          // fill blocks appended to kernel A

// ---- device scratch (no allocations; .bss zero at load, kernels self-clean) ----
__device__ unsigned g_h2[(size_t)N_MAX * 64];  // h' rows as packed half2 (64 uints/row)
__device__ int      g_cnt[N_MAX];
__device__ float    g_dis[N_MAX];
__device__ int      g_start[N_MAX];
__device__ int      g_cursor[N_MAX];
__device__ int      g_adj[E_MAX];
__device__ int      g_total;
__device__ float    g_colstats[2 * D];
// W16 in mma.sync B-fragment layout: word[(kc*128 + n)*8 + j] =
//   half2( W[kc*16 + koff][n], W[kc*16 + koff + 1][n] ),  koff = (j%4)*2 + (j/4)*8
__device__ unsigned gWf[8 * 128 * 8];

__device__ __forceinline__ float4 h8_to_f4(uint2 u) {
    float2 a = __half22float2(*(__half2*)&u.x);
    float2 b = __half22float2(*(__half2*)&u.y);
    return make_float4(a.x, a.y, b.x, b.y);
}

// hi/lo fp16 split of a float2 -> packed half2 words
__device__ __forceinline__ void split2(float2 q, unsigned& hi, unsigned& lo) {
    __half2 h = __floats2half2_rn(q.x, q.y);
    float2 hf = __half22float2(h);
    __half2 l = __floats2half2_rn(q.x - hf.x, q.y - hf.y);
    hi = *(unsigned*)&h;
    lo = *(unsigned*)&l;
}

#define MMA16816(d, a0, a1, a2, a3, b0, b1) \
    asm volatile("mma.sync.aligned.m16n8k16.row.col.f32.f16.f16.f32 " \
                 "{%0,%1,%2,%3}, {%4,%5,%6,%7}, {%8,%9}, {%0,%1,%2,%3};" \
                 : "+f"((d)[0]), "+f"((d)[1]), "+f"((d)[2]), "+f"((d)[3]) \
                 : "r"(a0), "r"(a1), "r"(a2), "r"(a3), "r"(b0), "r"(b1))

// ---------------------------------------------------------------------------
// K1: blocks [0,256): in-degree count; block 0 zeros colstats.
//     blocks [256,260): pack W into gWf (fragment-native layout).
// ---------------------------------------------------------------------------
__global__ void k_count(const int* __restrict__ pos, const float* __restrict__ Wg,
                        int E) {
    int b = blockIdx.x;
    if (b >= 256) {
        int part = b - 256;                         // 0..3, 2048 words each
        for (int wI = part * 2048 + threadIdx.x; wI < (part + 1) * 2048; wI += 256) {
            int kc = wI >> 10;                      // /1024
            int n  = (wI & 1023) >> 3;
            int j  = wI & 7;
            int k  = kc * 16 + (j & 3) * 2 + (j >> 2) * 8;
            __half2 v = __floats2half2_rn(Wg[(size_t)k * D + n],
                                          Wg[(size_t)(k + 1) * D + n]);
            gWf[wI] = *(unsigned*)&v;
        }
        return;
    }
    if (b == 0) g_colstats[threadIdx.x] = 0.0f;     // 256 == 2*D
    for (int e = b * 256 + threadIdx.x; e < E; e += 256 * 256)
        atomicAdd(&g_cnt[pos[(size_t)E + e]], 1);
}

// ---------------------------------------------------------------------------
// K2: segment allocation — block scan + one atomic ticket; dis; cursor
// ---------------------------------------------------------------------------
__global__ void k_alloc(int N) {
    __shared__ int sh[256];
    __shared__ int base;
    int t = threadIdx.x;
    int i = blockIdx.x * 256 + t;
    int c = (i < N) ? g_cnt[i] : 0;
    sh[t] = c;
    __syncthreads();
    for (int off = 1; off < 256; off <<= 1) {
        int v = (t >= off) ? sh[t - off] : 0;
        __syncthreads();
        sh[t] += v;
        __syncthreads();
    }
    if (t == 255) base = atomicAdd(&g_total, sh[255]);
    __syncthreads();
    if (i < N) {
        int start = base + sh[t] - c;
        g_start[i]  = start;
        g_cursor[i] = start;
        g_dis[i]    = rsqrtf(1.0f + (float)c);
    }
}

// ---------------------------------------------------------------------------
// Kernel A (block-specialized):
//   blocks [0, GB)     : tensor-core GEMM tile (128 rows x 128 cols, K=128)
//                        D = x_hi@W16 + x_lo@W16, fp32 accum; epilogue scales
//                        by dis[r] and packs half2 -> g_h2
//   blocks [GB, GB+FB) : CSC adjacency fill
// ---------------------------------------------------------------------------
__global__ void __launch_bounds__(256) kA(const float* __restrict__ x,
                                          const int* __restrict__ pos,
                                          int N, int E, int GB) {
    if (blockIdx.x >= GB) {
        int b = blockIdx.x - GB;
        for (int e = b * 256 + threadIdx.x; e < E; e += FB * 256) {
            int col = pos[(size_t)E + e];
            int p = atomicAdd(&g_cursor[col], 1);
            g_adj[p] = pos[e];
        }
        return;
    }

    __shared__ unsigned wsm[8192];       // 32 KB: gWf copy
    const int t = threadIdx.x;
    {
        const uint4* src = (const uint4*)gWf;
        uint4* dst = (uint4*)wsm;
#pragma unroll
        for (int u = 0; u < 8; u++) dst[t + u * 256] = src[t + u * 256];
    }
    __syncthreads();

    const int warp = t >> 5;
    const int lane = t & 31;
    const int g    = lane >> 2;          // 0..7
    const int qp   = lane & 3;           // 0..3
    const int r0   = blockIdx.x * 128;
    const int rLo  = r0 + warp * 16 + g;
    const int rHi  = rLo + 8;
    const bool okLo = rLo < N, okHi = rHi < N;

    const float* pLo = x + (size_t)rLo * D + qp * 2;
    const float* pHi = x + (size_t)rHi * D + qp * 2;

    float d[16][4];
#pragma unroll
    for (int nf = 0; nf < 16; nf++)
#pragma unroll
        for (int q = 0; q < 4; q++) d[nf][q] = 0.0f;

#pragma unroll
    for (int kc = 0; kc < 8; kc++) {
        float2 z = make_float2(0.f, 0.f);
        float2 q0 = okLo ? *(const float2*)(pLo + kc * 16)     : z;  // a0: row g,  k low
        float2 q1 = okHi ? *(const float2*)(pHi + kc * 16)     : z;  // a1: row g+8,k low
        float2 q2 = okLo ? *(const float2*)(pLo + kc * 16 + 8) : z;  // a2: row g,  k high
        float2 q3 = okHi ? *(const float2*)(pHi + kc * 16 + 8) : z;  // a3: row g+8,k high
        unsigned ah0, ah1, ah2, ah3, al0, al1, al2, al3;
        split2(q0, ah0, al0);
        split2(q1, ah1, al1);
        split2(q2, ah2, al2);
        split2(q3, ah3, al3);

        const unsigned* wrow = wsm + kc * 1024;
#pragma unroll
        for (int nf = 0; nf < 16; nf++) {
            int base = (nf * 8 + g) * 8 + qp;
            unsigned b0 = wrow[base];
            unsigned b1 = wrow[base + 4];
            MMA16816(d[nf], ah0, ah1, ah2, ah3, b0, b1);
            MMA16816(d[nf], al0, al1, al2, al3, b0, b1);
        }
    }

    // epilogue: scale by dis, pack half2, store
    float sLo = okLo ? g_dis[rLo] : 0.0f;
    float sHi = okHi ? g_dis[rHi] : 0.0f;
#pragma unroll
    for (int nf = 0; nf < 16; nf++) {
        int c0 = nf * 8 + qp * 2;        // even column
        if (okLo) {
            __half2 p = __floats2half2_rn(d[nf][0] * sLo, d[nf][1] * sLo);
            g_h2[(size_t)rLo * 64 + (c0 >> 1)] = *(unsigned*)&p;
        }
        if (okHi) {
            __half2 p = __floats2half2_rn(d[nf][2] * sHi, d[nf][3] * sHi);
            g_h2[(size_t)rHi * 64 + (c0 >> 1)] = *(unsigned*)&p;
        }
    }
}

// ---------------------------------------------------------------------------
// K3: gather — one node per warp; fp16 rows; HADD2 pair reduction + fp32
//     accumulation; fused stats.  out[c] = dis[c] * (h'[c] + sum_in h'[r])
// ---------------------------------------------------------------------------
__global__ void __launch_bounds__(256, 6) k_gather(float* __restrict__ out, int N) {
    __shared__ float ssum[8][128];
    __shared__ float ssq[8][128];
    int lane = threadIdx.x & 31;
    int w    = threadIdx.x >> 5;

    float4 cs = make_float4(0.f, 0.f, 0.f, 0.f);
    float4 cq = make_float4(0.f, 0.f, 0.f, 0.f);

    for (int node = blockIdx.x * 8 + w; node < N; node += gridDim.x * 8) {
        int start = g_start[node];
        int cnt   = g_cnt[node];

        float4 acc = h8_to_f4(*((const uint2*)(g_h2 + (size_t)node * 64) + lane));

        for (int j = 0; j < cnt; j += 32) {
            int m = min(32, cnt - j);
            int idx = (lane < m) ? g_adj[start + j + lane] : 0;
            int k = 0;
            for (; k + 4 <= m; k += 4) {
                int rA = __shfl_sync(0xffffffffu, idx, k + 0);
                int rB = __shfl_sync(0xffffffffu, idx, k + 1);
                int rC = __shfl_sync(0xffffffffu, idx, k + 2);
                int rD = __shfl_sync(0xffffffffu, idx, k + 3);
                uint2 uA = *((const uint2*)(g_h2 + (size_t)rA * 64) + lane);
                uint2 uB = *((const uint2*)(g_h2 + (size_t)rB * 64) + lane);
                uint2 uC = *((const uint2*)(g_h2 + (size_t)rC * 64) + lane);
                uint2 uD = *((const uint2*)(g_h2 + (size_t)rD * 64) + lane);
                uint2 pAB, pCD;
                *(__half2*)&pAB.x = __hadd2(*(__half2*)&uA.x, *(__half2*)&uB.x);
                *(__half2*)&pAB.y = __hadd2(*(__half2*)&uA.y, *(__half2*)&uB.y);
                *(__half2*)&pCD.x = __hadd2(*(__half2*)&uC.x, *(__half2*)&uD.x);
                *(__half2*)&pCD.y = __hadd2(*(__half2*)&uC.y, *(__half2*)&uD.y);
                float4 vAB = h8_to_f4(pAB);
                float4 vCD = h8_to_f4(pCD);
                acc.x += vAB.x + vCD.x;
                acc.y += vAB.y + vCD.y;
                acc.z += vAB.z + vCD.z;
                acc.w += vAB.w + vCD.w;
            }
            for (; k < m; k++) {
                int r = __shfl_sync(0xffffffffu, idx, k);
                float4 v = h8_to_f4(*((const uint2*)(g_h2 + (size_t)r * 64) + lane));
                acc.x += v.x; acc.y += v.y; acc.z += v.z; acc.w += v.w;
            }
        }

        float s = g_dis[node];
        float4 o = make_float4(acc.x * s, acc.y * s, acc.z * s, acc.w * s);
        *(float4*)(out + (size_t)node * D + lane * 4) = o;
        cs.x += o.x; cs.y += o.y; cs.z += o.z; cs.w += o.w;
        cq.x += o.x * o.x; cq.y += o.y * o.y;
        cq.z += o.z * o.z; cq.w += o.w * o.w;
    }

    *(float4*)&ssum[w][lane * 4] = cs;
    *(float4*)&ssq[w][lane * 4]  = cq;
    __syncthreads();
    int t = threadIdx.x;
    if (t < D) {
        float a = 0.f, b = 0.f;
#pragma unroll
        for (int w2 = 0; w2 < 8; w2++) { a += ssum[w2][t]; b += ssq[w2][t]; }
        atomicAdd(&g_colstats[t], a);
        atomicAdd(&g_colstats[D + t], b);
    }
}

// ---------------------------------------------------------------------------
// K4: BN (training mode, biased var) + ReLU in place; 2-way MLP; self-clean
// ---------------------------------------------------------------------------
__global__ void k_final(const float* __restrict__ gamma,
                        const float* __restrict__ beta,
                        float* __restrict__ out, int N) {
    __shared__ float sscale[D], sshift[D];
    int t = threadIdx.x;
    if (t < D) {
        float invN = 1.0f / (float)N;
        float mean = g_colstats[t] * invN;
        float var  = g_colstats[D + t] * invN - mean * mean;
        float inv  = rsqrtf(var + 1e-5f);
        float sc   = gamma[t] * inv;
        sscale[t]  = sc;
        sshift[t]  = beta[t] - mean * sc;
    }
    __syncthreads();

    int gid = blockIdx.x * blockDim.x + t;
    if (gid < N) g_cnt[gid] = 0;
    if (gid == 0) g_total = 0;

    size_t total4 = (size_t)N * (D / 4);
    size_t stride = (size_t)gridDim.x * blockDim.x;
    for (size_t i = (size_t)blockIdx.x * blockDim.x + t; i < total4; i += stride * 2) {
        size_t i2 = i + stride;
        float4 v = ((float4*)out)[i];
        float4 u;
        bool has2 = i2 < total4;
        if (has2) u = ((float4*)out)[i2];
        int c  = (int)(i  & 31) * 4;
        v.x = fmaxf(v.x * sscale[c + 0] + sshift[c + 0], 0.0f);
        v.y = fmaxf(v.y * sscale[c + 1] + sshift[c + 1], 0.0f);
        v.z = fmaxf(v.z * sscale[c + 2] + sshift[c + 2], 0.0f);
        v.w = fmaxf(v.w * sscale[c + 3] + sshift[c + 3], 0.0f);
        ((float4*)out)[i] = v;
        if (has2) {
            int c2 = (int)(i2 & 31) * 4;
            u.x = fmaxf(u.x * sscale[c2 + 0] + sshift[c2 + 0], 0.0f);
            u.y = fmaxf(u.y * sscale[c2 + 1] + sshift[c2 + 1], 0.0f);
            u.z = fmaxf(u.z * sscale[c2 + 2] + sshift[c2 + 2], 0.0f);
            u.w = fmaxf(u.w * sscale[c2 + 3] + sshift[c2 + 3], 0.0f);
            ((float4*)out)[i2] = u;
        }
    }
}

// ---------------------------------------------------------------------------
extern "C" void kernel_launch(void* const* d_in, const int* in_sizes, int n_in,
                              void* d_out, int out_size) {
    const float* x     = (const float*)d_in[0];
    const int*   pos   = (const int*)d_in[1];   // int32 (JAX canonicalizes int64)
    // d_in[2] = neg_edge_index: weight 0 => no-op, skipped
    const float* W     = (const float*)d_in[3];
    // d_in[4] = b: cancels exactly inside BatchNorm, skipped
    const float* gamma = (const float*)d_in[5];
    const float* beta  = (const float*)d_in[6];
    float*       out   = (float*)d_out;

    const int N  = in_sizes[0] / D;
    const int E  = in_sizes[1] / 2;
    const int GB = (N + 127) / 128;

    k_count <<<260, 256>>>(pos, W, E);
    k_alloc <<<(N + 255) / 256, 256>>>(N);
    kA      <<<GB + FB, 256>>>(x, pos, N, E, GB);
    k_gather<<<888, 256>>>(out, N);     // 148 SMs x 6 blocks
    k_final <<<1184, 256>>>(gamma, beta, out, N);
}

// round 16
// speedup vs baseline: 1.3518x; 1.3518x over previous
#include <cuda_runtime.h>
#include <cuda_fp16.h>
#include <cstdint>

#define D 128
#define N_MAX 50064
#define E_MAX 500000

// ---- device scratch (no allocations; .bss zero at load, kernels self-clean) ----
__device__ unsigned g_h2[(size_t)N_MAX * 64];  // h' rows as packed half2 (64 uints/row)
__device__ int      g_cnt[N_MAX];
__device__ float    g_dis[N_MAX];
__device__ int      g_start[N_MAX];
__device__ int      g_cursor[N_MAX];
__device__ int      g_adj[E_MAX];
__device__ int      g_total;
__device__ float    g_colstats[2 * D];
// W16 in mma.sync B-fragment layout: word[(kc*128 + n)*8 + j] =
//   half2( W[kc*16 + koff][n], W[kc*16 + koff + 1][n] ),  koff = (j%4)*2 + (j/4)*8
__device__ unsigned gWf[8 * 128 * 8];

__device__ __forceinline__ float4 h8_to_f4(uint2 u) {
    float2 a = __half22float2(*(__half2*)&u.x);
    float2 b = __half22float2(*(__half2*)&u.y);
    return make_float4(a.x, a.y, b.x, b.y);
}

__device__ __forceinline__ void split2(float2 q, unsigned& hi, unsigned& lo) {
    __half2 h = __floats2half2_rn(q.x, q.y);
    float2 hf = __half22float2(h);
    __half2 l = __floats2half2_rn(q.x - hf.x, q.y - hf.y);
    hi = *(unsigned*)&h;
    lo = *(unsigned*)&l;
}

#define MMA16816(d, a0, a1, a2, a3, b0, b1) \
    asm volatile("mma.sync.aligned.m16n8k16.row.col.f32.f16.f16.f32 " \
                 "{%0,%1,%2,%3}, {%4,%5,%6,%7}, {%8,%9}, {%0,%1,%2,%3};" \
                 : "+f"((d)[0]), "+f"((d)[1]), "+f"((d)[2]), "+f"((d)[3]) \
                 : "r"(a0), "r"(a1), "r"(a2), "r"(a3), "r"(b0), "r"(b1))

// ---------------------------------------------------------------------------
// K1: blocks [0,256): in-degree count; block 0 zeros colstats.
//     blocks [256,260): pack W into gWf (fragment-native layout).
// ---------------------------------------------------------------------------
__global__ void k_count(const int* __restrict__ pos, const float* __restrict__ Wg,
                        int E) {
    int b = blockIdx.x;
    if (b >= 256) {
        int part = b - 256;                         // 0..3, 2048 words each
        for (int wI = part * 2048 + threadIdx.x; wI < (part + 1) * 2048; wI += 256) {
            int kc = wI >> 10;
            int n  = (wI & 1023) >> 3;
            int j  = wI & 7;
            int k  = kc * 16 + (j & 3) * 2 + (j >> 2) * 8;
            __half2 v = __floats2half2_rn(Wg[(size_t)k * D + n],
                                          Wg[(size_t)(k + 1) * D + n]);
            gWf[wI] = *(unsigned*)&v;
        }
        return;
    }
    if (b == 0) g_colstats[threadIdx.x] = 0.0f;     // 256 == 2*D
    for (int e = b * 256 + threadIdx.x; e < E; e += 256 * 256)
        atomicAdd(&g_cnt[pos[(size_t)E + e]], 1);
}

// ---------------------------------------------------------------------------
// K2: segment allocation — block scan + one atomic ticket; dis; cursor
// ---------------------------------------------------------------------------
__global__ void k_alloc(int N) {
    __shared__ int sh[256];
    __shared__ int base;
    int t = threadIdx.x;
    int i = blockIdx.x * 256 + t;
    int c = (i < N) ? g_cnt[i] : 0;
    sh[t] = c;
    __syncthreads();
    for (int off = 1; off < 256; off <<= 1) {
        int v = (t >= off) ? sh[t - off] : 0;
        __syncthreads();
        sh[t] += v;
        __syncthreads();
    }
    if (t == 255) base = atomicAdd(&g_total, sh[255]);
    __syncthreads();
    if (i < N) {
        int start = base + sh[t] - c;
        g_start[i]  = start;
        g_cursor[i] = start;
        g_dis[i]    = rsqrtf(1.0f + (float)c);
    }
}

// ---------------------------------------------------------------------------
// K3: CSC adjacency fill (standalone — no smem/reg footprint from GEMM)
// ---------------------------------------------------------------------------
__global__ void k_fill(const int* __restrict__ pos, int E) {
    for (int e = blockIdx.x * 256 + threadIdx.x; e < E; e += gridDim.x * 256) {
        int col = pos[(size_t)E + e];
        int p = atomicAdd(&g_cursor[col], 1);
        g_adj[p] = pos[e];
    }
}

// ---------------------------------------------------------------------------
// K4 (kA): pure tensor-core GEMM (128 rows x 128 cols, K=128 per block)
//     D = x_hi@W16 + x_lo@W16, fp32 accum; epilogue scales by dis[r],
//     packs half2 -> g_h2
// ---------------------------------------------------------------------------
__global__ void __launch_bounds__(256) kA(const float* __restrict__ x, int N) {
    __shared__ unsigned wsm[8192];       // 32 KB: gWf copy
    const int t = threadIdx.x;
    {
        const uint4* src = (const uint4*)gWf;
        uint4* dst = (uint4*)wsm;
#pragma unroll
        for (int u = 0; u < 8; u++) dst[t + u * 256] = src[t + u * 256];
    }
    __syncthreads();

    const int warp = t >> 5;
    const int lane = t & 31;
    const int g    = lane >> 2;          // 0..7
    const int qp   = lane & 3;           // 0..3
    const int r0   = blockIdx.x * 128;
    const int rLo  = r0 + warp * 16 + g;
    const int rHi  = rLo + 8;
    const bool okLo = rLo < N, okHi = rHi < N;

    const float* pLo = x + (size_t)rLo * D + qp * 2;
    const float* pHi = x + (size_t)rHi * D + qp * 2;

    float d[16][4];
#pragma unroll
    for (int nf = 0; nf < 16; nf++)
#pragma unroll
        for (int q = 0; q < 4; q++) d[nf][q] = 0.0f;

#pragma unroll
    for (int kc = 0; kc < 8; kc++) {
        float2 z = make_float2(0.f, 0.f);
        float2 q0 = okLo ? *(const float2*)(pLo + kc * 16)     : z;
        float2 q1 = okHi ? *(const float2*)(pHi + kc * 16)     : z;
        float2 q2 = okLo ? *(const float2*)(pLo + kc * 16 + 8) : z;
        float2 q3 = okHi ? *(const float2*)(pHi + kc * 16 + 8) : z;
        unsigned ah0, ah1, ah2, ah3, al0, al1, al2, al3;
        split2(q0, ah0, al0);
        split2(q1, ah1, al1);
        split2(q2, ah2, al2);
        split2(q3, ah3, al3);

        const unsigned* wrow = wsm + kc * 1024;
#pragma unroll
        for (int nf = 0; nf < 16; nf++) {
            int base = (nf * 8 + g) * 8 + qp;
            unsigned b0 = wrow[base];
            unsigned b1 = wrow[base + 4];
            MMA16816(d[nf], ah0, ah1, ah2, ah3, b0, b1);
            MMA16816(d[nf], al0, al1, al2, al3, b0, b1);
        }
    }

    float sLo = okLo ? g_dis[rLo] : 0.0f;
    float sHi = okHi ? g_dis[rHi] : 0.0f;
#pragma unroll
    for (int nf = 0; nf < 16; nf++) {
        int c0 = nf * 8 + qp * 2;
        if (okLo) {
            __half2 p = __floats2half2_rn(d[nf][0] * sLo, d[nf][1] * sLo);
            g_h2[(size_t)rLo * 64 + (c0 >> 1)] = *(unsigned*)&p;
        }
        if (okHi) {
            __half2 p = __floats2half2_rn(d[nf][2] * sHi, d[nf][3] * sHi);
            g_h2[(size_t)rHi * 64 + (c0 >> 1)] = *(unsigned*)&p;
        }
    }
}

// ---------------------------------------------------------------------------
// K5: gather — one node per warp; fp16 rows; HADD2 pair reduction + fp32
//     accumulation; fused stats.  out[c] = dis[c] * (h'[c] + sum_in h'[r])
// ---------------------------------------------------------------------------
__global__ void __launch_bounds__(256, 6) k_gather(float* __restrict__ out, int N) {
    __shared__ float ssum[8][128];
    __shared__ float ssq[8][128];
    int lane = threadIdx.x & 31;
    int w    = threadIdx.x >> 5;

    float4 cs = make_float4(0.f, 0.f, 0.f, 0.f);
    float4 cq = make_float4(0.f, 0.f, 0.f, 0.f);

    for (int node = blockIdx.x * 8 + w; node < N; node += gridDim.x * 8) {
        int start = g_start[node];
        int cnt   = g_cnt[node];

        float4 acc = h8_to_f4(*((const uint2*)(g_h2 + (size_t)node * 64) + lane));

        for (int j = 0; j < cnt; j += 32) {
            int m = min(32, cnt - j);
            int idx = (lane < m) ? g_adj[start + j + lane] : 0;
            int k = 0;
            for (; k + 4 <= m; k += 4) {
                int rA = __shfl_sync(0xffffffffu, idx, k + 0);
                int rB = __shfl_sync(0xffffffffu, idx, k + 1);
                int rC = __shfl_sync(0xffffffffu, idx, k + 2);
                int rD = __shfl_sync(0xffffffffu, idx, k + 3);
                uint2 uA = *((const uint2*)(g_h2 + (size_t)rA * 64) + lane);
                uint2 uB = *((const uint2*)(g_h2 + (size_t)rB * 64) + lane);
                uint2 uC = *((const uint2*)(g_h2 + (size_t)rC * 64) + lane);
                uint2 uD = *((const uint2*)(g_h2 + (size_t)rD * 64) + lane);
                uint2 pAB, pCD;
                *(__half2*)&pAB.x = __hadd2(*(__half2*)&uA.x, *(__half2*)&uB.x);
                *(__half2*)&pAB.y = __hadd2(*(__half2*)&uA.y, *(__half2*)&uB.y);
                *(__half2*)&pCD.x = __hadd2(*(__half2*)&uC.x, *(__half2*)&uD.x);
                *(__half2*)&pCD.y = __hadd2(*(__half2*)&uC.y, *(__half2*)&uD.y);
                float4 vAB = h8_to_f4(pAB);
                float4 vCD = h8_to_f4(pCD);
                acc.x += vAB.x + vCD.x;
                acc.y += vAB.y + vCD.y;
                acc.z += vAB.z + vCD.z;
                acc.w += vAB.w + vCD.w;
            }
            for (; k < m; k++) {
                int r = __shfl_sync(0xffffffffu, idx, k);
                float4 v = h8_to_f4(*((const uint2*)(g_h2 + (size_t)r * 64) + lane));
                acc.x += v.x; acc.y += v.y; acc.z += v.z; acc.w += v.w;
            }
        }

        float s = g_dis[node];
        float4 o = make_float4(acc.x * s, acc.y * s, acc.z * s, acc.w * s);
        *(float4*)(out + (size_t)node * D + lane * 4) = o;
        cs.x += o.x; cs.y += o.y; cs.z += o.z; cs.w += o.w;
        cq.x += o.x * o.x; cq.y += o.y * o.y;
        cq.z += o.z * o.z; cq.w += o.w * o.w;
    }

    *(float4*)&ssum[w][lane * 4] = cs;
    *(float4*)&ssq[w][lane * 4]  = cq;
    __syncthreads();
    int t = threadIdx.x;
    if (t < D) {
        float a = 0.f, b = 0.f;
#pragma unroll
        for (int w2 = 0; w2 < 8; w2++) { a += ssum[w2][t]; b += ssq[w2][t]; }
        atomicAdd(&g_colstats[t], a);
        atomicAdd(&g_colstats[D + t], b);
    }
}

// ---------------------------------------------------------------------------
// K6: BN (training mode, biased var) + ReLU in place; 2-way MLP; self-clean
// ---------------------------------------------------------------------------
__global__ void k_final(const float* __restrict__ gamma,
                        const float* __restrict__ beta,
                        float* __restrict__ out, int N) {
    __shared__ float sscale[D], sshift[D];
    int t = threadIdx.x;
    if (t < D) {
        float invN = 1.0f / (float)N;
        float mean = g_colstats[t] * invN;
        float var  = g_colstats[D + t] * invN - mean * mean;
        float inv  = rsqrtf(var + 1e-5f);
        float sc   = gamma[t] * inv;
        sscale[t]  = sc;
        sshift[t]  = beta[t] - mean * sc;
    }
    __syncthreads();

    int gid = blockIdx.x * blockDim.x + t;
    if (gid < N) g_cnt[gid] = 0;
    if (gid == 0) g_total = 0;

    size_t total4 = (size_t)N * (D / 4);
    size_t stride = (size_t)gridDim.x * blockDim.x;
    for (size_t i = (size_t)blockIdx.x * blockDim.x + t; i < total4; i += stride * 2) {
        size_t i2 = i + stride;
        float4 v = ((float4*)out)[i];
        float4 u;
        bool has2 = i2 < total4;
        if (has2) u = ((float4*)out)[i2];
        int c  = (int)(i  & 31) * 4;
        v.x = fmaxf(v.x * sscale[c + 0] + sshift[c + 0], 0.0f);
        v.y = fmaxf(v.y * sscale[c + 1] + sshift[c + 1], 0.0f);
        v.z = fmaxf(v.z * sscale[c + 2] + sshift[c + 2], 0.0f);
        v.w = fmaxf(v.w * sscale[c + 3] + sshift[c + 3], 0.0f);
        ((float4*)out)[i] = v;
        if (has2) {
            int c2 = (int)(i2 & 31) * 4;
            u.x = fmaxf(u.x * sscale[c2 + 0] + sshift[c2 + 0], 0.0f);
            u.y = fmaxf(u.y * sscale[c2 + 1] + sshift[c2 + 1], 0.0f);
            u.z = fmaxf(u.z * sscale[c2 + 2] + sshift[c2 + 2], 0.0f);
            u.w = fmaxf(u.w * sscale[c2 + 3] + sshift[c2 + 3], 0.0f);
            ((float4*)out)[i2] = u;
        }
    }
}

// ---------------------------------------------------------------------------
extern "C" void kernel_launch(void* const* d_in, const int* in_sizes, int n_in,
                              void* d_out, int out_size) {
    const float* x     = (const float*)d_in[0];
    const int*   pos   = (const int*)d_in[1];   // int32 (JAX canonicalizes int64)
    // d_in[2] = neg_edge_index: weight 0 => no-op, skipped
    const float* W     = (const float*)d_in[3];
    // d_in[4] = b: cancels exactly inside BatchNorm, skipped
    const float* gamma = (const float*)d_in[5];
    const float* beta  = (const float*)d_in[6];
    float*       out   = (float*)d_out;

    const int N  = in_sizes[0] / D;
    const int E  = in_sizes[1] / 2;
    const int GB = (N + 127) / 128;

    k_count <<<260, 256>>>(pos, W, E);
    k_alloc <<<(N + 255) / 256, 256>>>(N);
    k_fill  <<<296, 256>>>(pos, E);
    kA      <<<GB, 256>>>(x, N);
    k_gather<<<888, 256>>>(out, N);     // 148 SMs x 6 blocks
    k_final <<<1184, 256>>>(gamma, beta, out, N);
}